// round 1
// baseline (speedup 1.0000x reference)
#include <cuda_runtime.h>

#define B 16
#define CI 64
#define CO 64
#define HH 192
#define WW 192
#define KDY 4
#define HID 17
#define GROUPS 8
#define CPG 8
#define PLANE (HH*WW)
#define TEMPERATURE 30.0f
#define EPS 1e-5f
#define SLOPE 0.01f

// ---- device scratch (no allocations allowed) ----
__device__ float g_pooled[B][CI];
__device__ float g_attn[B][KDY];
__device__ float g_filters[B][CI][9][CO];   // [b][ci][r][co]  (co contiguous for LDS.128)
__device__ float g_stats[B][GROUPS][2];     // sum, sumsq

// ============================================================
// K1: global average pool over H,W per (b, c)
// ============================================================
__global__ void pool_kernel(const float* __restrict__ x) {
    int bc = blockIdx.x;                       // b*CI + c
    const float4* p = (const float4*)(x + (size_t)bc * PLANE);
    float s = 0.f;
    for (int i = threadIdx.x; i < PLANE/4; i += 256) {
        float4 v = p[i];
        s += v.x + v.y + v.z + v.w;
    }
    __shared__ float sm[8];
    #pragma unroll
    for (int o = 16; o > 0; o >>= 1) s += __shfl_down_sync(~0u, s, o);
    if ((threadIdx.x & 31) == 0) sm[threadIdx.x >> 5] = s;
    __syncthreads();
    if (threadIdx.x == 0) {
        float t = 0.f;
        #pragma unroll
        for (int w = 0; w < 8; w++) t += sm[w];
        g_pooled[bc / CI][bc % CI] = t / (float)PLANE;
    }
}

// ============================================================
// K2a: attention MLP + softmax(T=30); also zero group stats
// ============================================================
__global__ void attn_kernel(const float* __restrict__ w1,
                            const float* __restrict__ w2,
                            const float* __restrict__ b2) {
    int t = threadIdx.x;
    if (t < B * GROUPS * 2) ((float*)g_stats)[t] = 0.f;
    if (t < B) {
        float h[HID];
        #pragma unroll
        for (int j = 0; j < HID; j++) {
            float a = 0.f;
            #pragma unroll 8
            for (int c = 0; c < CI; c++) a += g_pooled[t][c] * w1[j*CI + c];
            h[j] = a > 0.f ? a : 0.f;
        }
        float sc[KDY];
        float m = -1e30f;
        #pragma unroll
        for (int k = 0; k < KDY; k++) {
            float a = b2[k];
            #pragma unroll
            for (int j = 0; j < HID; j++) a += h[j] * w2[k*HID + j];
            sc[k] = a / TEMPERATURE;
            m = fmaxf(m, sc[k]);
        }
        float se = 0.f;
        #pragma unroll
        for (int k = 0; k < KDY; k++) { sc[k] = expf(sc[k] - m); se += sc[k]; }
        #pragma unroll
        for (int k = 0; k < KDY; k++) g_attn[t][k] = sc[k] / se;
    }
}

// ============================================================
// K2b: synthesize per-sample filters: F[b] = sum_k attn[b][k] * W[k]
//      output layout [b][ci][r][co]
// ============================================================
__global__ void filt_kernel(const float* __restrict__ W) {
    int idx = blockIdx.x * 256 + threadIdx.x;   // linear over (b, ci, r, co)
    if (idx >= B*CI*9*CO) return;
    int co = idx % CO;
    int r  = (idx / CO) % 9;
    int ci = (idx / (CO*9)) % CI;
    int b  = idx / (CO*9*CI);
    float a0 = g_attn[b][0], a1 = g_attn[b][1], a2 = g_attn[b][2], a3 = g_attn[b][3];
    size_t base = ((size_t)co*CI + ci)*9 + r;          // W is [k][co][ci][3][3]
    const size_t ks = (size_t)CO*CI*9;
    float f = a0*W[base] + a1*W[base+ks] + a2*W[base+2*ks] + a3*W[base+3*ks];
    ((float*)g_filters)[idx] = f;
}

// ============================================================
// K3: per-sample 3x3 conv (stride 1, pad 1), register-tiled.
// Block: (spatial 32x32 tile, 16 c_out, sample b). 256 threads,
// each thread: 2x2 pixel quad x 16 c_out accumulators.
// Epilogue: write raw y to d_out + atomic group-stat partials.
// ============================================================
#define TILE 32
#define CIC 8
__global__ void __launch_bounds__(256)
conv_kernel(const float* __restrict__ x, float* __restrict__ out) {
    __shared__ float sX[CIC][34][36];   // padded rows (36) to dodge conflicts
    __shared__ float sF[CIC][9][16];
    __shared__ float red[8][4];

    int b   = blockIdx.z;
    int cob = blockIdx.y * 16;
    int tx0 = (blockIdx.x % 6) * TILE;
    int ty0 = (blockIdx.x / 6) * TILE;
    int tid = threadIdx.x;
    int qx = tid & 15, qy = tid >> 4;

    float acc[16][4];
    #pragma unroll
    for (int i = 0; i < 16; i++)
        #pragma unroll
        for (int j = 0; j < 4; j++) acc[i][j] = 0.f;

    const float* xb = x + (size_t)b * CI * PLANE;

    for (int cc = 0; cc < CI; cc += CIC) {
        // stage input tile (with halo, zero-padded at image border)
        for (int i = tid; i < CIC*34*34; i += 256) {
            int ci = i / (34*34);
            int t2 = i % (34*34);
            int y = t2 / 34, xx = t2 % 34;
            int gy = ty0 + y - 1, gx = tx0 + xx - 1;
            float v = 0.f;
            if (gy >= 0 && gy < HH && gx >= 0 && gx < WW)
                v = xb[(size_t)(cc+ci)*PLANE + gy*WW + gx];
            sX[ci][y][xx] = v;
        }
        // stage filters for this (ci chunk, co tile)
        for (int i = tid; i < CIC*9*16; i += 256) {
            int ci = i / (9*16);
            int r  = (i / 16) % 9;
            int co = i % 16;
            sF[ci][r][co] = g_filters[b][cc+ci][r][cob+co];
        }
        __syncthreads();

        #pragma unroll
        for (int ci = 0; ci < CIC; ci++) {
            float xp[4][4];
            #pragma unroll
            for (int rr = 0; rr < 4; rr++) {
                float2 u = *(const float2*)&sX[ci][2*qy+rr][2*qx];
                float2 v = *(const float2*)&sX[ci][2*qy+rr][2*qx+2];
                xp[rr][0]=u.x; xp[rr][1]=u.y; xp[rr][2]=v.x; xp[rr][3]=v.y;
            }
            #pragma unroll
            for (int kh = 0; kh < 3; kh++) {
                #pragma unroll
                for (int kw = 0; kw < 3; kw++) {
                    int r = kh*3+kw;
                    #pragma unroll
                    for (int c4 = 0; c4 < 4; c4++) {
                        float4 f = *(const float4*)&sF[ci][r][c4*4];
                        float fv[4] = {f.x, f.y, f.z, f.w};
                        #pragma unroll
                        for (int u2 = 0; u2 < 4; u2++) {
                            int co = c4*4 + u2;
                            acc[co][0] += xp[kh  ][kw  ] * fv[u2];
                            acc[co][1] += xp[kh  ][kw+1] * fv[u2];
                            acc[co][2] += xp[kh+1][kw  ] * fv[u2];
                            acc[co][3] += xp[kh+1][kw+1] * fv[u2];
                        }
                    }
                }
            }
        }
        __syncthreads();
    }

    // write raw conv output (pre-GN) into d_out
    #pragma unroll
    for (int co = 0; co < 16; co++) {
        #pragma unroll
        for (int dy = 0; dy < 2; dy++) {
            float2 v; v.x = acc[co][dy*2]; v.y = acc[co][dy*2+1];
            size_t o = ((size_t)(b*CO + cob + co)*HH + (ty0 + 2*qy + dy))*WW
                       + tx0 + 2*qx;
            *(float2*)(out + o) = v;
        }
    }

    // fused GroupNorm partial stats (co 0..7 -> group by*2, 8..15 -> by*2+1)
    float s0=0.f, q0=0.f, s1=0.f, q1=0.f;
    #pragma unroll
    for (int co = 0; co < 8; co++)
        #pragma unroll
        for (int p = 0; p < 4; p++) { float v = acc[co][p]; s0 += v; q0 += v*v; }
    #pragma unroll
    for (int co = 8; co < 16; co++)
        #pragma unroll
        for (int p = 0; p < 4; p++) { float v = acc[co][p]; s1 += v; q1 += v*v; }
    #pragma unroll
    for (int o = 16; o > 0; o >>= 1) {
        s0 += __shfl_down_sync(~0u, s0, o); q0 += __shfl_down_sync(~0u, q0, o);
        s1 += __shfl_down_sync(~0u, s1, o); q1 += __shfl_down_sync(~0u, q1, o);
    }
    if ((tid & 31) == 0) {
        int w = tid >> 5;
        red[w][0]=s0; red[w][1]=q0; red[w][2]=s1; red[w][3]=q1;
    }
    __syncthreads();
    if (tid < 4) {
        float a = 0.f;
        #pragma unroll
        for (int w = 0; w < 8; w++) a += red[w][tid];
        int g = blockIdx.y*2 + (tid >> 1);
        atomicAdd(&g_stats[b][g][tid & 1], a);
    }
}

// ============================================================
// K4: in-place GroupNorm + affine + LeakyReLU over d_out
// ============================================================
__global__ void norm_kernel(float* __restrict__ out,
                            const float* __restrict__ gamma,
                            const float* __restrict__ beta) {
    int idx = blockIdx.x * 256 + threadIdx.x;   // float4 index
    const int PL4 = PLANE / 4;
    int clin = idx / PL4;
    int co = clin % CO;
    int b  = clin / CO;
    int g  = co >> 3;
    float s = g_stats[b][g][0], q = g_stats[b][g][1];
    const float invN = 1.f / (float)(CPG * PLANE);
    float mean = s * invN;
    float var  = q * invN - mean*mean;
    float rstd = rsqrtf(var + EPS);
    float ga = gamma[co], be = beta[co];
    float4 v = ((float4*)out)[idx];
    float* pv = (float*)&v;
    #pragma unroll
    for (int i = 0; i < 4; i++) {
        float yn = (pv[i] - mean) * rstd * ga + be;
        pv[i] = yn >= 0.f ? yn : SLOPE * yn;
    }
    ((float4*)out)[idx] = v;
}

// ============================================================
extern "C" void kernel_launch(void* const* d_in, const int* in_sizes, int n_in,
                              void* d_out, int out_size) {
    const float* x  = (const float*)d_in[0];
    const float* w1 = (const float*)d_in[1];
    const float* w2 = (const float*)d_in[2];
    const float* b2 = (const float*)d_in[3];
    const float* W  = (const float*)d_in[4];
    const float* ga = (const float*)d_in[5];
    const float* be = (const float*)d_in[6];
    float* out = (float*)d_out;

    pool_kernel<<<B*CI, 256>>>(x);
    attn_kernel<<<1, 256>>>(w1, w2, b2);
    filt_kernel<<<(B*CI*9*CO + 255)/256, 256>>>(W);
    conv_kernel<<<dim3(36, 4, 16), 256>>>(x, out);
    norm_kernel<<<(B*CO*PLANE/4)/256, 256>>>(out, ga, be);
}

// round 3
// speedup vs baseline: 2.3950x; 2.3950x over previous
#include <cuda_runtime.h>
#include <cstdint>

#define B 16
#define CI 64
#define CO 64
#define HH 192
#define WW 192
#define KDY 4
#define HID 17
#define GROUPS 8
#define CPG 8
#define PLANE (HH*WW)
#define TEMPERATURE 30.0f
#define EPS 1e-5f
#define SLOPE 0.01f

// ---- device scratch ----
__device__ float g_pooled[B][CI];
__device__ float g_attn[B][KDY];
__device__ float g_filters[B*9*CI*CO];      // [b][tap][ci][co], tf32-rounded
__device__ float g_stats[B][GROUPS][2];     // sum, sumsq

__device__ __forceinline__ uint32_t f2tf32(float v) {
    uint32_t u;
    asm("cvt.rna.tf32.f32 %0, %1;" : "=r"(u) : "f"(v));
    return u;
}
__device__ __forceinline__ void mma8(float* c, const uint32_t* a, const uint32_t* b) {
    asm volatile(
        "mma.sync.aligned.m16n8k8.row.col.f32.tf32.tf32.f32 "
        "{%0,%1,%2,%3}, {%4,%5,%6,%7}, {%8,%9}, {%0,%1,%2,%3};"
        : "+f"(c[0]), "+f"(c[1]), "+f"(c[2]), "+f"(c[3])
        : "r"(a[0]), "r"(a[1]), "r"(a[2]), "r"(a[3]), "r"(b[0]), "r"(b[1]));
}

// ============================================================
// K1: global average pool
// ============================================================
__global__ void pool_kernel(const float* __restrict__ x) {
    int bc = blockIdx.x;
    const float4* p = (const float4*)(x + (size_t)bc * PLANE);
    float s = 0.f;
    for (int i = threadIdx.x; i < PLANE/4; i += 256) {
        float4 v = p[i];
        s += v.x + v.y + v.z + v.w;
    }
    __shared__ float sm[8];
    #pragma unroll
    for (int o = 16; o > 0; o >>= 1) s += __shfl_down_sync(~0u, s, o);
    if ((threadIdx.x & 31) == 0) sm[threadIdx.x >> 5] = s;
    __syncthreads();
    if (threadIdx.x == 0) {
        float t = 0.f;
        #pragma unroll
        for (int w = 0; w < 8; w++) t += sm[w];
        g_pooled[bc / CI][bc % CI] = t / (float)PLANE;
    }
}

// ============================================================
// K2a: attention MLP + softmax; zero group stats
// ============================================================
__global__ void attn_kernel(const float* __restrict__ w1,
                            const float* __restrict__ w2,
                            const float* __restrict__ b2) {
    int t = threadIdx.x;
    if (t < B * GROUPS * 2) ((float*)g_stats)[t] = 0.f;
    if (t < B) {
        float h[HID];
        #pragma unroll
        for (int j = 0; j < HID; j++) {
            float a = 0.f;
            #pragma unroll 8
            for (int c = 0; c < CI; c++) a += g_pooled[t][c] * w1[j*CI + c];
            h[j] = a > 0.f ? a : 0.f;
        }
        float sc[KDY];
        float m = -1e30f;
        #pragma unroll
        for (int k = 0; k < KDY; k++) {
            float a = b2[k];
            #pragma unroll
            for (int j = 0; j < HID; j++) a += h[j] * w2[k*HID + j];
            sc[k] = a / TEMPERATURE;
            m = fmaxf(m, sc[k]);
        }
        float se = 0.f;
        #pragma unroll
        for (int k = 0; k < KDY; k++) { sc[k] = expf(sc[k] - m); se += sc[k]; }
        #pragma unroll
        for (int k = 0; k < KDY; k++) g_attn[t][k] = sc[k] / se;
    }
}

// ============================================================
// K2b: filter synthesis -> [b][tap][ci][co], tf32-rounded
// ============================================================
__global__ void filt_kernel(const float* __restrict__ W) {
    int idx = blockIdx.x * 256 + threadIdx.x;   // b,tap,ci,co
    if (idx >= B*9*CI*CO) return;
    int co  = idx & 63;
    int ci  = (idx >> 6) & 63;
    int tap = (idx >> 12) % 9;
    int b   = idx / (9*CI*CO);
    const int ks = CO*CI*9;
    float a0 = g_attn[b][0], a1 = g_attn[b][1], a2 = g_attn[b][2], a3 = g_attn[b][3];
    int wb = ((co*CI) + ci)*9 + tap;            // W[k][co][ci][tap]
    float f = a0*W[wb] + a1*W[wb+ks] + a2*W[wb+2*ks] + a3*W[wb+3*ks];
    g_filters[idx] = __uint_as_float(f2tf32(f));
}

// ============================================================
// K3: implicit-GEMM conv via mma.sync tf32 (legacy tensor path).
// CTA: sample b, 256 pixels (4 rows x 64 cols), 64 c_out.
// 8 warps, each m32 x n64. K=576 ordered (tap, ci); per k8-step
// (dy,dx) fixed -> A frags read straight from raw x tile in smem.
// ============================================================
#define CCH 16
#define XTW 68
__global__ void __launch_bounds__(256, 2)
conv_kernel(const float* __restrict__ x, float* __restrict__ out) {
    __shared__ float sx[CCH][6][XTW];       // ci-stride 408 (==24 mod 32): conflict-free
    __shared__ float sb[3][CCH][72];        // ci-stride 72  (==8  mod 32): conflict-free

    const int tid = threadIdx.x;
    const int w = tid >> 5, lane = tid & 31;
    const int tig = lane & 3, grp = lane >> 2;
    const int b  = blockIdx.z;
    const int y0 = blockIdx.y * 4;
    const int x0 = blockIdx.x * 64;
    const int wrow = w >> 1;                // image row within 4-row block
    const int wx = (w & 1) * 32;            // x offset of warp's 32 pixels

    float acc[2][8][4];
    #pragma unroll
    for (int mt = 0; mt < 2; mt++)
        #pragma unroll
        for (int nt = 0; nt < 8; nt++)
            #pragma unroll
            for (int r = 0; r < 4; r++) acc[mt][nt][r] = 0.f;

    for (int cc = 0; cc < 4; cc++) {
        __syncthreads();
        // stage raw x tile: ci chunk cc*16, rows y0-1..y0+4, cols x0-1..x0+64
        const float* xb = x + ((size_t)b*CI + cc*CCH)*PLANE;
        for (int i = tid; i < CCH*6*66; i += 256) {
            int ci  = i / 396;
            int r2  = i - ci*396;
            int row = r2 / 66;
            int col = r2 - row*66;
            int gy = y0 - 1 + row, gx = x0 - 1 + col;
            float v = 0.f;
            if ((unsigned)gy < (unsigned)HH && (unsigned)gx < (unsigned)WW)
                v = xb[ci*PLANE + gy*WW + gx];
            sx[ci][row][col] = __uint_as_float(f2tf32(v));
        }
        for (int tg = 0; tg < 3; tg++) {    // tg = dy+1
            __syncthreads();
            // stage filters: taps tg*3..+2, ci cc*16..+15, all co
            const float* fb = g_filters + ((b*9 + tg*3)*CI + cc*CCH)*CO;
            for (int i = tid; i < 3*CCH*CO; i += 256) {
                int tap = i >> 10;
                int ci  = (i >> 6) & 15;
                int co  = i & 63;
                sb[tap][ci][co] = fb[(tap*CI + ci)*CO + co];
            }
            __syncthreads();
            #pragma unroll
            for (int tloc = 0; tloc < 3; tloc++) {   // tloc = dx+1
                #pragma unroll
                for (int kk = 0; kk < 2; kk++) {
                    // A fragments
                    uint32_t a[2][4];
                    const uint32_t* ap =
                        (const uint32_t*)&sx[kk*8 + tig][wrow + tg][wx + tloc + grp];
                    #pragma unroll
                    for (int mt = 0; mt < 2; mt++) {
                        a[mt][0] = ap[mt*16];
                        a[mt][1] = ap[mt*16 + 8];
                        a[mt][2] = ap[mt*16 +     4*6*XTW];
                        a[mt][3] = ap[mt*16 + 8 + 4*6*XTW];
                    }
                    // B fragments
                    uint32_t bf[8][2];
                    const uint32_t* bp =
                        (const uint32_t*)&sb[tloc][kk*8 + tig][grp];
                    #pragma unroll
                    for (int nt = 0; nt < 8; nt++) {
                        bf[nt][0] = bp[nt*8];
                        bf[nt][1] = bp[nt*8 + 4*72];
                    }
                    #pragma unroll
                    for (int mt = 0; mt < 2; mt++)
                        #pragma unroll
                        for (int nt = 0; nt < 8; nt++)
                            mma8(acc[mt][nt], a[mt], bf[nt]);
                }
            }
        }
    }

    // ---- epilogue: store raw conv + fused GroupNorm partials ----
    const int gy = y0 + wrow;
    float s[8], q[8];
    #pragma unroll
    for (int g = 0; g < 8; g++) { s[g] = 0.f; q[g] = 0.f; }

    float* ob = out + ((size_t)b*CO)*PLANE + gy*WW;
    #pragma unroll
    for (int mt = 0; mt < 2; mt++) {
        #pragma unroll
        for (int nt = 0; nt < 8; nt++) {
            #pragma unroll
            for (int r = 0; r < 4; r++) {
                float v = acc[mt][nt][r];
                int gx = x0 + wx + mt*16 + grp + ((r >> 1) << 3);
                int co = nt*8 + tig*2 + (r & 1);
                ob[co*PLANE + gx] = v;
                s[nt] += v;
                q[nt] += v*v;
            }
        }
    }
    #pragma unroll
    for (int o = 16; o > 0; o >>= 1) {
        #pragma unroll
        for (int g = 0; g < 8; g++) {
            s[g] += __shfl_down_sync(~0u, s[g], o);
            q[g] += __shfl_down_sync(~0u, q[g], o);
        }
    }
    if (lane == 0) {
        #pragma unroll
        for (int g = 0; g < 8; g++) {
            atomicAdd(&g_stats[b][g][0], s[g]);
            atomicAdd(&g_stats[b][g][1], q[g]);
        }
    }
}

// ============================================================
// K4: in-place GroupNorm + affine + LeakyReLU
// ============================================================
__global__ void norm_kernel(float* __restrict__ out,
                            const float* __restrict__ gamma,
                            const float* __restrict__ beta) {
    int idx = blockIdx.x * 256 + threadIdx.x;
    const int PL4 = PLANE / 4;
    int clin = idx / PL4;
    int co = clin % CO;
    int b  = clin / CO;
    int g  = co >> 3;
    float s = g_stats[b][g][0], q = g_stats[b][g][1];
    const float invN = 1.f / (float)(CPG * PLANE);
    float mean = s * invN;
    float var  = q * invN - mean*mean;
    float rstd = rsqrtf(var + EPS);
    float ga = gamma[co], be = beta[co];
    float4 v = ((float4*)out)[idx];
    float* pv = (float*)&v;
    #pragma unroll
    for (int i = 0; i < 4; i++) {
        float yn = (pv[i] - mean) * rstd * ga + be;
        pv[i] = yn >= 0.f ? yn : SLOPE * yn;
    }
    ((float4*)out)[idx] = v;
}

// ============================================================
extern "C" void kernel_launch(void* const* d_in, const int* in_sizes, int n_in,
                              void* d_out, int out_size) {
    const float* x  = (const float*)d_in[0];
    const float* w1 = (const float*)d_in[1];
    const float* w2 = (const float*)d_in[2];
    const float* b2 = (const float*)d_in[3];
    const float* W  = (const float*)d_in[4];
    const float* ga = (const float*)d_in[5];
    const float* be = (const float*)d_in[6];
    float* out = (float*)d_out;

    pool_kernel<<<B*CI, 256>>>(x);
    attn_kernel<<<1, 256>>>(w1, w2, b2);
    filt_kernel<<<(B*9*CI*CO + 255)/256, 256>>>(W);
    conv_kernel<<<dim3(3, 48, B), 256>>>(x, out);
    norm_kernel<<<(B*CO*PLANE/4)/256, 256>>>(out, ga, be);
}

// round 4
// speedup vs baseline: 2.9339x; 1.2250x over previous
#include <cuda_runtime.h>
#include <cstdint>

#define B 16
#define CI 64
#define CO 64
#define HH 192
#define WW 192
#define KDY 4
#define HID 17
#define GROUPS 8
#define CPG 8
#define PLANE (HH*WW)
#define TEMPERATURE 30.0f
#define EPS 1e-5f
#define SLOPE 0.01f

// conv tiling
#define CCH 8                      // ci per chunk
#define NCH 8                      // chunks
#define SXPS 440                   // sx plane stride (floats) per ci: 6*72 + 8 pad
#define SXB (CCH*SXPS*4)           // 14080 B per sx buffer
#define SBROW 72                   // sb row stride (floats)
#define SBB (9*CCH*SBROW*4)        // 20736 B per sb buffer
#define SMEM_DYN (2*SXB + 2*SBB)   // 69632 B

// ---- device scratch ----
__device__ float g_pooled[B][CI];
__device__ float g_attn[B][KDY];
__device__ __align__(16) float g_filters[B*NCH*9*CCH*CO];  // [b][cc][tap][ci8][co]
__device__ float g_stats[B][GROUPS][2];

__device__ __forceinline__ uint32_t f2tf32(float v) {
    uint32_t u;
    asm("cvt.rna.tf32.f32 %0, %1;" : "=r"(u) : "f"(v));
    return u;
}
__device__ __forceinline__ void mma8(float* c, const uint32_t* a, const uint32_t* b) {
    asm volatile(
        "mma.sync.aligned.m16n8k8.row.col.f32.tf32.tf32.f32 "
        "{%0,%1,%2,%3}, {%4,%5,%6,%7}, {%8,%9}, {%0,%1,%2,%3};"
        : "+f"(c[0]), "+f"(c[1]), "+f"(c[2]), "+f"(c[3])
        : "r"(a[0]), "r"(a[1]), "r"(a[2]), "r"(a[3]), "r"(b[0]), "r"(b[1]));
}
__device__ __forceinline__ void cpa16(void* dst, const void* src, int sz) {
    uint32_t d = (uint32_t)__cvta_generic_to_shared(dst);
    asm volatile("cp.async.cg.shared.global [%0], [%1], 16, %2;"
                 :: "r"(d), "l"(src), "r"(sz) : "memory");
}
__device__ __forceinline__ void cpa_commit() {
    asm volatile("cp.async.commit_group;" ::: "memory");
}
__device__ __forceinline__ void cpa_wait1() {
    asm volatile("cp.async.wait_group 1;" ::: "memory");
}

// ============================================================
// K1: global average pool
// ============================================================
__global__ void pool_kernel(const float* __restrict__ x) {
    int bc = blockIdx.x;
    const float4* p = (const float4*)(x + (size_t)bc * PLANE);
    float s = 0.f;
    for (int i = threadIdx.x; i < PLANE/4; i += 256) {
        float4 v = p[i];
        s += v.x + v.y + v.z + v.w;
    }
    __shared__ float sm[8];
    #pragma unroll
    for (int o = 16; o > 0; o >>= 1) s += __shfl_down_sync(~0u, s, o);
    if ((threadIdx.x & 31) == 0) sm[threadIdx.x >> 5] = s;
    __syncthreads();
    if (threadIdx.x == 0) {
        float t = 0.f;
        #pragma unroll
        for (int w = 0; w < 8; w++) t += sm[w];
        g_pooled[bc / CI][bc % CI] = t / (float)PLANE;
    }
}

// ============================================================
// K2a: attention MLP + softmax; zero group stats
// ============================================================
__global__ void attn_kernel(const float* __restrict__ w1,
                            const float* __restrict__ w2,
                            const float* __restrict__ b2) {
    int t = threadIdx.x;
    if (t < B * GROUPS * 2) ((float*)g_stats)[t] = 0.f;
    if (t < B) {
        float h[HID];
        #pragma unroll
        for (int j = 0; j < HID; j++) {
            float a = 0.f;
            #pragma unroll 8
            for (int c = 0; c < CI; c++) a += g_pooled[t][c] * w1[j*CI + c];
            h[j] = a > 0.f ? a : 0.f;
        }
        float sc[KDY];
        float m = -1e30f;
        #pragma unroll
        for (int k = 0; k < KDY; k++) {
            float a = b2[k];
            #pragma unroll
            for (int j = 0; j < HID; j++) a += h[j] * w2[k*HID + j];
            sc[k] = a / TEMPERATURE;
            m = fmaxf(m, sc[k]);
        }
        float se = 0.f;
        #pragma unroll
        for (int k = 0; k < KDY; k++) { sc[k] = expf(sc[k] - m); se += sc[k]; }
        #pragma unroll
        for (int k = 0; k < KDY; k++) g_attn[t][k] = sc[k] / se;
    }
}

// ============================================================
// K2b: filter synthesis -> staging layout [b][cc][tap][ci8][co]
// ============================================================
__global__ void filt_kernel(const float* __restrict__ W) {
    int idx = blockIdx.x * 256 + threadIdx.x;     // exact grid, no guard needed
    int co  = idx & 63;
    int ci8 = (idx >> 6) & 7;
    int t3  = idx >> 9;
    int tap = t3 % 9;
    int t4  = t3 / 9;
    int cc  = t4 & 7;
    int b   = t4 >> 3;
    int ci  = cc*CCH + ci8;
    const int ks = CO*CI*9;
    float a0 = g_attn[b][0], a1 = g_attn[b][1], a2 = g_attn[b][2], a3 = g_attn[b][3];
    int wb = (co*CI + ci)*9 + tap;                // W[k][co][ci][tap]
    float f = a0*W[wb] + a1*W[wb+ks] + a2*W[wb+2*ks] + a3*W[wb+3*ks];
    g_filters[idx] = __uint_as_float(f2tf32(f));
}

// ============================================================
// K3: implicit-GEMM tf32 conv, cp.async double-buffered pipeline.
// CTA: sample b, 256 pixels (4 rows x 64 cols), 64 c_out, 8 warps.
// Chunk = 8 ci: x tile (8ci x 6rows x 72cols, plane stride 440)
// + filters (9 taps x 8ci x 64co, row stride 72), both via cp.async.
// 9 fully-unrolled k8-steps per chunk.
// ============================================================
__global__ void __launch_bounds__(256, 2)
conv_kernel(const float* __restrict__ x, float* __restrict__ out) {
    extern __shared__ __align__(16) unsigned char dynsm[];
    float* sxb[2] = {(float*)dynsm, (float*)(dynsm + SXB)};
    float* sbb[2] = {(float*)(dynsm + 2*SXB), (float*)(dynsm + 2*SXB + SBB)};

    const int tid = threadIdx.x;
    const int w = tid >> 5, lane = tid & 31;
    const int tig = lane & 3, grp = lane >> 2;
    const int b  = blockIdx.z;
    const int y0 = blockIdx.y * 4;
    const int x0 = blockIdx.x * 64;
    const int wrow = w >> 1;
    const int wx = (w & 1) * 32;

    float acc[2][8][4];
    #pragma unroll
    for (int mt = 0; mt < 2; mt++)
        #pragma unroll
        for (int nt = 0; nt < 8; nt++)
            #pragma unroll
            for (int r = 0; r < 4; r++) acc[mt][nt][r] = 0.f;

    const float* xb = x + (size_t)b*CI*PLANE;
    const float* fbase = g_filters + (size_t)b*NCH*9*CCH*CO;

    // ---- staging lambda ----
    auto stage = [&](int cc, int buf) {
        float* sx = sxb[buf];
        // x tile: 8ci x 6rows x 18 16B-chunks
        for (int i = tid; i < CCH*6*18; i += 256) {
            int ci  = i / 108;
            int r2  = i - ci*108;
            int row = r2 / 18;
            int c16 = r2 - row*18;
            int gy  = y0 - 1 + row;
            int gxs = x0 - 4 + c16*4;
            int ok  = ((unsigned)gy < (unsigned)HH) &
                      ((unsigned)gxs <= (unsigned)(WW-4));
            const float* src = ok ? (xb + (size_t)(cc*CCH+ci)*PLANE + gy*WW + gxs)
                                  : xb;
            cpa16(sx + ci*SXPS + row*SBROW + c16*4, src, ok ? 16 : 0);
        }
        // filters: contiguous 72 rows x 16 chunks
        float* sb = sbb[buf];
        const float* fsrc = fbase + (size_t)cc*9*CCH*CO;
        for (int j = tid; j < 72*16; j += 256) {
            int row = j >> 4, c = j & 15;
            cpa16(sb + row*SBROW + c*4, fsrc + row*CO + c*4, 16);
        }
    };

    // ---- compute lambda: 9 unrolled k8-steps over a staged chunk ----
    auto compute = [&](int buf) {
        const uint32_t* ax = (const uint32_t*)(sxb[buf]) +
                             tig*SXPS + wrow*SBROW + (wx + grp + 3);
        const uint32_t* bb = (const uint32_t*)(sbb[buf]) + tig*SBROW + grp;
        #pragma unroll
        for (int tap = 0; tap < 9; tap++) {
            const int tg = tap / 3, tloc = tap - tg*3;
            const uint32_t* ap = ax + tg*SBROW + tloc;
            const uint32_t* bp = bb + tap*(CCH*SBROW);
            uint32_t a[2][4];
            #pragma unroll
            for (int mt = 0; mt < 2; mt++) {
                a[mt][0] = ap[mt*16];
                a[mt][1] = ap[mt*16 + 8];
                a[mt][2] = ap[mt*16 + 4*SXPS];
                a[mt][3] = ap[mt*16 + 4*SXPS + 8];
            }
            uint32_t bf[8][2];
            #pragma unroll
            for (int nt = 0; nt < 8; nt++) {
                bf[nt][0] = bp[nt*8];
                bf[nt][1] = bp[nt*8 + 4*SBROW];
            }
            #pragma unroll
            for (int mt = 0; mt < 2; mt++)
                #pragma unroll
                for (int nt = 0; nt < 8; nt++)
                    mma8(acc[mt][nt], a[mt], bf[nt]);
        }
    };

    // ---- pipeline ----
    stage(0, 0);
    cpa_commit();
    for (int ch = 0; ch < NCH; ch++) {
        if (ch + 1 < NCH) stage(ch + 1, (ch + 1) & 1);
        cpa_commit();
        cpa_wait1();
        __syncthreads();
        compute(ch & 1);
        __syncthreads();
    }

    // ---- epilogue: store raw conv + fused GroupNorm partials ----
    const int gy = y0 + wrow;
    float s[8], q[8];
    #pragma unroll
    for (int g = 0; g < 8; g++) { s[g] = 0.f; q[g] = 0.f; }

    float* ob = out + (size_t)b*CO*PLANE + gy*WW;
    #pragma unroll
    for (int mt = 0; mt < 2; mt++) {
        #pragma unroll
        for (int nt = 0; nt < 8; nt++) {
            #pragma unroll
            for (int r = 0; r < 4; r++) {
                float v = acc[mt][nt][r];
                int gx = x0 + wx + mt*16 + grp + ((r >> 1) << 3);
                int co = nt*8 + tig*2 + (r & 1);
                ob[co*PLANE + gx] = v;
                s[nt] += v;
                q[nt] += v*v;
            }
        }
    }
    #pragma unroll
    for (int o = 16; o > 0; o >>= 1) {
        #pragma unroll
        for (int g = 0; g < 8; g++) {
            s[g] += __shfl_down_sync(~0u, s[g], o);
            q[g] += __shfl_down_sync(~0u, q[g], o);
        }
    }
    if (lane == 0) {
        #pragma unroll
        for (int g = 0; g < 8; g++) {
            atomicAdd(&g_stats[b][g][0], s[g]);
            atomicAdd(&g_stats[b][g][1], q[g]);
        }
    }
}

// ============================================================
// K4: in-place GroupNorm + affine + LeakyReLU
// ============================================================
__global__ void norm_kernel(float* __restrict__ out,
                            const float* __restrict__ gamma,
                            const float* __restrict__ beta) {
    int idx = blockIdx.x * 256 + threadIdx.x;
    const int PL4 = PLANE / 4;
    int clin = idx / PL4;
    int co = clin % CO;
    int b  = clin / CO;
    int g  = co >> 3;
    float s = g_stats[b][g][0], q = g_stats[b][g][1];
    const float invN = 1.f / (float)(CPG * PLANE);
    float mean = s * invN;
    float var  = q * invN - mean*mean;
    float rstd = rsqrtf(var + EPS);
    float ga = gamma[co], be = beta[co];
    float4 v = ((float4*)out)[idx];
    float* pv = (float*)&v;
    #pragma unroll
    for (int i = 0; i < 4; i++) {
        float yn = (pv[i] - mean) * rstd * ga + be;
        pv[i] = yn >= 0.f ? yn : SLOPE * yn;
    }
    ((float4*)out)[idx] = v;
}

// ============================================================
extern "C" void kernel_launch(void* const* d_in, const int* in_sizes, int n_in,
                              void* d_out, int out_size) {
    const float* x  = (const float*)d_in[0];
    const float* w1 = (const float*)d_in[1];
    const float* w2 = (const float*)d_in[2];
    const float* b2 = (const float*)d_in[3];
    const float* W  = (const float*)d_in[4];
    const float* ga = (const float*)d_in[5];
    const float* be = (const float*)d_in[6];
    float* out = (float*)d_out;

    cudaFuncSetAttribute(conv_kernel,
                         cudaFuncAttributeMaxDynamicSharedMemorySize, SMEM_DYN);

    pool_kernel<<<B*CI, 256>>>(x);
    attn_kernel<<<1, 256>>>(w1, w2, b2);
    filt_kernel<<<(B*NCH*9*CCH*CO)/256, 256>>>(W);
    conv_kernel<<<dim3(3, 48, B), 256, SMEM_DYN>>>(x, out);
    norm_kernel<<<(B*CO*PLANE/4)/256, 256>>>(out, ga, be);
}